// round 13
// baseline (speedup 1.0000x reference)
#include <cuda_runtime.h>
#include <cooperative_groups.h>
#include <cstdint>

namespace cg = cooperative_groups;

#define NB 4
#define NS 8192
#define ND 512
#define NP 32
#define NT (NP + NS)          // 8224
#define LN_EPS 1e-5f
#define ZCH 512               // chunks per batch (16 rows each)
#define CROWS 16
#define KZ 8                  // split-K for GEMVs
#define KS (ND / KZ)          // 64
#define NQ (ND / 4)           // 128 column-quads
#define NGRID 148

// Scratch (device-side only)
__device__ float4 g_part4[ZCH][NB * NQ];  // per-chunk partial x sums (4MB, L2)
__device__ float4 g_vp4[KZ][NB * NQ];     // split-K vbar partials
__device__ float4 g_yp4[KZ][NB * NQ];     // split-K y partials

__device__ __forceinline__ float4 f4add(float4 a, float4 b) {
    return make_float4(a.x + b.x, a.y + b.y, a.z + b.z, a.w + b.w);
}

// ---------------- role R: reduce 16-row chunks of x for batch b -------------
__device__ __forceinline__ void do_R(const float4* __restrict__ x4,
                                     int b, int bid, int b0, int nb, int tid) {
    const int d4 = tid & 127;
    const int nq = nb * 4;
    const int q0 = (bid - b0) * 4 + (tid >> 7);
    for (int u = q0; u < ZCH; u += nq) {
        const float4* p = x4 + ((size_t)b * NS + (size_t)u * CROWS) * NQ + d4;
        float4 v[16];
#pragma unroll
        for (int j = 0; j < 16; j++) v[j] = p[(size_t)j * NQ];
        float4 r = f4add(f4add(f4add(v[0], v[1]),  f4add(v[2], v[3])),
                         f4add(f4add(v[4], v[5]),  f4add(v[6], v[7])));
        float4 s = f4add(f4add(f4add(v[8], v[9]),  f4add(v[10], v[11])),
                         f4add(f4add(v[12], v[13]), f4add(v[14], v[15])));
        g_part4[u][b * NQ + d4] = f4add(r, s);
    }
}

// ---------------- role GA: cbar slice + GEMV1 partial (split z) -------------
__device__ __forceinline__ void do_GA(const float* __restrict__ pm,
                                      const float4* __restrict__ Wv4,
                                      int b, int z, int t,
                                      float (*spart)[KS], float* sk,
                                      float4 (*sacc)[NQ]) {
    {   // cbar slice: 8 groups x 64 chunks each (+ pm rows)
        const int kl = t & 63, g = t >> 6;
        const int k  = z * KS + kl;
        const float* gp = (const float*)g_part4 + b * ND + k;
        float a = 0.f;
#pragma unroll 8
        for (int c = 0; c < ZCH / 8; c++)
            a += gp[(size_t)(g * (ZCH / 8) + c) * (NB * ND)];
#pragma unroll
        for (int p = 0; p < NP / 8; p++)
            a += pm[(g * (NP / 8) + p) * ND + k];
        spart[g][kl] = a;
    }
    __syncthreads();
    if (t < KS) {
        float a = 0.f;
#pragma unroll
        for (int g = 0; g < 8; g++) a += spart[g][t];
        sk[t] = a / (float)NT;
    }
    __syncthreads();
    {   // GEMV1 partial: quad outputs, 4-way k-split, 16-deep chains
        const int q = t & 127, s = t >> 7;
        const int k0 = z * KS + s * 16;
        float4 acc = make_float4(0.f, 0.f, 0.f, 0.f);
#pragma unroll
        for (int j = 0; j < 16; j++) {
            float4 w = Wv4[(size_t)(k0 + j) * NQ + q];
            float  c = sk[s * 16 + j];
            acc.x += c * w.x; acc.y += c * w.y; acc.z += c * w.z; acc.w += c * w.w;
        }
        sacc[s][q] = acc;
    }
    __syncthreads();
    if (t < NQ) {
        float4 r = f4add(f4add(sacc[0][t], sacc[1][t]),
                         f4add(sacc[2][t], sacc[3][t]));
        g_vp4[z][b * NQ + t] = r;
    }
    __syncthreads();
}

// block-wide sum over 512 threads, deterministic
__device__ __forceinline__ float bsum512(float v, float* wred, float* bc) {
    const int t = threadIdx.x, lane = t & 31, wid = t >> 5;
#pragma unroll
    for (int off = 16; off > 0; off >>= 1)
        v += __shfl_xor_sync(0xffffffffu, v, off);
    if (lane == 0) wred[wid] = v;
    __syncthreads();
    if (wid == 0) {
        float s = (lane < 16) ? wred[lane] : 0.f;
#pragma unroll
        for (int off = 8; off > 0; off >>= 1)
            s += __shfl_xor_sync(0xffffffffu, s, off);
        if (lane == 0) *bc = s;
    }
    __syncthreads();
    return *bc;
}

// ---------------- role GB: vbar combine + LN + GEMV2 partial ----------------
__device__ __forceinline__ void do_GB(const float* __restrict__ bv,
                                      const float* __restrict__ gamma,
                                      const float* __restrict__ beta,
                                      const float4* __restrict__ Wout4,
                                      int b, int z, int t,
                                      float* ssn, float4 (*sacc)[NQ],
                                      float* wred, float* sbc) {
    float vb = bv[t];
#pragma unroll
    for (int c = 0; c < KZ; c++)
        vb += ((const float*)g_vp4[c])[b * ND + t];

    const float mu   = bsum512(vb, wred, &sbc[0]) / (float)ND;
    const float diff = vb - mu;
    const float var  = bsum512(diff * diff, wred, &sbc[1]) / (float)ND;
    const float inv  = rsqrtf(var + LN_EPS);
    const float nrm  = diff * inv * gamma[t] + beta[t];
    __syncthreads();
    if ((t >> 6) == z) ssn[t & 63] = nrm;
    __syncthreads();
    {
        const int q = t & 127, s = t >> 7;
        const int k0 = z * KS + s * 16;
        float4 acc = make_float4(0.f, 0.f, 0.f, 0.f);
#pragma unroll
        for (int j = 0; j < 16; j++) {
            float4 w = Wout4[(size_t)(k0 + j) * NQ + q];
            float  c = ssn[s * 16 + j];
            acc.x += c * w.x; acc.y += c * w.y; acc.z += c * w.z; acc.w += c * w.w;
        }
        sacc[s][q] = acc;
    }
    __syncthreads();
    if (t < NQ) {
        float4 r = f4add(f4add(sacc[0][t], sacc[1][t]),
                         f4add(sacc[2][t], sacc[3][t]));
        g_yp4[z][b * NQ + t] = r;
    }
    __syncthreads();
}

// ---------------- role W: combine y + broadcast batch b ---------------------
__device__ __forceinline__ void do_W(const float4* __restrict__ bout4,
                                     float4* __restrict__ out4,
                                     int b, int bid, int b0, int nb, int tid,
                                     float4* sy) {
    if (tid < NQ) {
        float4 a = bout4[tid];
#pragma unroll
        for (int z = 0; z < KZ; z++) a = f4add(a, g_yp4[z][b * NQ + tid]);
        sy[tid] = a;
    }
    __syncthreads();
    const float4 val = sy[tid & 127];          // invariant per thread
    const int r = tid >> 7;
    float4* ob = out4 + (size_t)b * NT * NQ + (size_t)r * NQ + (tid & 127);
    for (int g = bid - b0; g < NT / 4; g += nb) {   // 4-row groups (8KB each)
        float4* o = ob + (size_t)g * (4 * NQ);
        asm volatile("st.global.cs.v4.f32 [%0], {%1, %2, %3, %4};"
                     :: "l"(o), "f"(val.x), "f"(val.y), "f"(val.z), "f"(val.w)
                     : "memory");
    }
    __syncthreads();
}

// ---------------------------------------------------------------------------
// Single persistent cooperative kernel: 7-slot software pipeline over batches.
//  S1 R0 | S2 GA0,R1 | S3 GB0,GA1,R2 | S4 GB1,GA2,R3,W0
//  S5 GB2,GA3,W1 | S6 GB3,W2 | S7 W3
// ---------------------------------------------------------------------------
__global__ void __launch_bounds__(512, 1)
titan_fused_kernel(const float4* __restrict__ x4,
                   const float*  __restrict__ pm,
                   const float4* __restrict__ Wv4,
                   const float*  __restrict__ bv,
                   const float*  __restrict__ gamma,
                   const float*  __restrict__ beta,
                   const float4* __restrict__ Wout4,
                   const float4* __restrict__ bout4,
                   float4*       __restrict__ out4) {
    cg::grid_group grid = cg::this_grid();
    const int bid = blockIdx.x, tid = threadIdx.x;

    __shared__ float  spart[8][KS];
    __shared__ float  sk[KS];
    __shared__ float4 sacc[4][NQ];
    __shared__ float  ssn[KS];
    __shared__ float  wred[16], sbc[2];
    __shared__ float4 sy[NQ];

    // S1
    do_R(x4, 0, bid, 0, NGRID, tid);
    grid.sync();
    // S2
    if (bid < 8) do_GA(pm, Wv4, 0, bid, tid, spart, sk, sacc);
    else         do_R(x4, 1, bid, 8, NGRID - 8, tid);
    grid.sync();
    // S3
    if (bid < 8)       do_GB(bv, gamma, beta, Wout4, 0, bid, tid, ssn, sacc, wred, sbc);
    else if (bid < 16) do_GA(pm, Wv4, 1, bid - 8, tid, spart, sk, sacc);
    else               do_R(x4, 2, bid, 16, NGRID - 16, tid);
    grid.sync();
    // S4 (duplex slot: R3 reads while W0 writes)
    if (bid < 8)       do_GB(bv, gamma, beta, Wout4, 1, bid, tid, ssn, sacc, wred, sbc);
    else if (bid < 16) do_GA(pm, Wv4, 2, bid - 8, tid, spart, sk, sacc);
    else if (bid < 82) do_R(x4, 3, bid, 16, 66, tid);
    else               do_W(bout4, out4, 0, bid, 82, 66, tid, sy);
    grid.sync();
    // S5
    if (bid < 8)       do_GB(bv, gamma, beta, Wout4, 2, bid, tid, ssn, sacc, wred, sbc);
    else if (bid < 16) do_GA(pm, Wv4, 3, bid - 8, tid, spart, sk, sacc);
    else               do_W(bout4, out4, 1, bid, 16, NGRID - 16, tid, sy);
    grid.sync();
    // S6
    if (bid < 8) do_GB(bv, gamma, beta, Wout4, 3, bid, tid, ssn, sacc, wred, sbc);
    else         do_W(bout4, out4, 2, bid, 8, NGRID - 8, tid, sy);
    grid.sync();
    // S7
    do_W(bout4, out4, 3, bid, 0, NGRID, tid, sy);
}

// ---------------------------------------------------------------------------
extern "C" void kernel_launch(void* const* d_in, const int* in_sizes, int n_in,
                              void* d_out, int out_size) {
    const float4* x4    = (const float4*)d_in[0];
    const float*  pm    = (const float*)d_in[1];
    // d_in[2]=Wk, [3]=bk, [6]=Wq, [7]=bq unused: softmax over zero-state and
    // constant-in-m logits collapse to uniform attention weights.
    const float4* Wv4   = (const float4*)d_in[4];
    const float*  bv    = (const float*)d_in[5];
    const float*  gamma = (const float*)d_in[8];
    const float*  beta  = (const float*)d_in[9];
    const float4* Wout4 = (const float4*)d_in[10];
    const float4* bout4 = (const float4*)d_in[11];
    float4*       out4  = (float4*)d_out;

    void* args[] = { (void*)&x4, (void*)&pm, (void*)&Wv4, (void*)&bv,
                     (void*)&gamma, (void*)&beta, (void*)&Wout4,
                     (void*)&bout4, (void*)&out4 };
    cudaLaunchCooperativeKernel((const void*)titan_fused_kernel,
                                dim3(NGRID), dim3(512), args, 0, 0);
}

// round 15
// speedup vs baseline: 1.3578x; 1.3578x over previous
#include <cuda_runtime.h>
#include <cooperative_groups.h>
#include <cstdint>

namespace cg = cooperative_groups;

#define NB 4
#define NS 8192
#define ND 512
#define NP 32
#define NT (NP + NS)          // 8224
#define LN_EPS 1e-5f
#define ZCH 128               // chunks per batch for reduce (64 rows each)
#define CROWS (NS / ZCH)      // 64
#define KZ 8                  // split-K for GEMVs
#define KS (ND / KZ)          // 64
#define NQ (ND / 4)           // 128 column-quads
#define NGRID 148
#define WCH 257               // write chunks per batch (32 rows each)

// Scratch (device-side only)
__device__ float4 g_part4[ZCH][NB * NQ];  // per-chunk partial x sums
__device__ float4 g_vp4[KZ][NB * NQ];     // split-K vbar partials
__device__ float4 g_yp4[KZ][NB * NQ];     // split-K y partials

__device__ __forceinline__ float4 f4add(float4 a, float4 b) {
    return make_float4(a.x + b.x, a.y + b.y, a.z + b.z, a.w + b.w);
}

// block-wide sum over 512 threads, deterministic
__device__ __forceinline__ float bsum512(float v, float* wred, float* bc) {
    const int t = threadIdx.x, lane = t & 31, wid = t >> 5;
#pragma unroll
    for (int off = 16; off > 0; off >>= 1)
        v += __shfl_xor_sync(0xffffffffu, v, off);
    if (lane == 0) wred[wid] = v;
    __syncthreads();
    if (wid == 0) {
        float s = (lane < 16) ? wred[lane] : 0.f;
#pragma unroll
        for (int off = 8; off > 0; off >>= 1)
            s += __shfl_xor_sync(0xffffffffu, s, off);
        if (lane == 0) *bc = s;
    }
    __syncthreads();
    return *bc;
}

// ---------------------------------------------------------------------------
// Single cooperative kernel, strictly sequential phases (no slot pipelining):
//  S1: reduce (all blocks, R12 shape)  -> g_part4
//  S2: GA: cbar + GEMV1 (32 blocks)    -> g_vp4
//  S3: GB: LN + GEMV2   (32 blocks)    -> g_yp4
//  S4: W: broadcast     (all blocks, R7 shape, st.cs)
// ---------------------------------------------------------------------------
__global__ void __launch_bounds__(512, 1)
titan_fused_kernel(const float4* __restrict__ x4,
                   const float*  __restrict__ pm,
                   const float4* __restrict__ Wv4,
                   const float*  __restrict__ bv,
                   const float*  __restrict__ gamma,
                   const float*  __restrict__ beta,
                   const float4* __restrict__ Wout4,
                   const float4* __restrict__ bout4,
                   float4*       __restrict__ out4) {
    cg::grid_group grid = cg::this_grid();
    const int bid = blockIdx.x, tid = threadIdx.x;

    __shared__ float  spart[8][KS];
    __shared__ float  sk[KS];
    __shared__ float4 sacc[4][NQ];
    __shared__ float  ssn[KS];
    __shared__ float  wred[16], sbc[2];

    // ---------------- S1: reduce x (identical to R12 reduce, 14.3us) -------
    {
        const int d4 = tid & 127;
        const int g  = tid >> 7;                 // quarter 0..3
        const int u  = g * NGRID + bid;          // interleaved unit id
        if (u < NB * ZCH) {
            const int b = u >> 7;
            const int z = u & (ZCH - 1);
            const float4* p = x4 + ((size_t)(b * NS + z * CROWS)) * NQ + d4;
            float4 a[4];
#pragma unroll
            for (int j = 0; j < 4; j++) a[j] = make_float4(0.f, 0.f, 0.f, 0.f);
#pragma unroll
            for (int i = 0; i < CROWS; i += 16) {
                float4 v[16];
#pragma unroll
                for (int j = 0; j < 16; j++)
                    v[j] = p[(size_t)(i + j) * NQ];
#pragma unroll
                for (int j = 0; j < 16; j++) {
                    a[j & 3].x += v[j].x;
                    a[j & 3].y += v[j].y;
                    a[j & 3].z += v[j].z;
                    a[j & 3].w += v[j].w;
                }
            }
            float4 r;
            r.x = (a[0].x + a[1].x) + (a[2].x + a[3].x);
            r.y = (a[0].y + a[1].y) + (a[2].y + a[3].y);
            r.z = (a[0].z + a[1].z) + (a[2].z + a[3].z);
            r.w = (a[0].w + a[1].w) + (a[2].w + a[3].w);
            g_part4[z][b * NQ + d4] = r;
        }
    }
    grid.sync();

    // ---------------- S2: GA — cbar slice + GEMV1 partial (32 blocks) ------
    if (bid < NB * KZ) {
        const int b = bid & 3, z = bid >> 2, t = tid;
        {   // cbar slice: 8 groups x 16 chunks (+ pm rows)
            const int kl = t & 63, g = t >> 6;
            const int k  = z * KS + kl;
            const float* gp = (const float*)g_part4 + b * ND + k;
            float a = 0.f;
#pragma unroll
            for (int c = 0; c < ZCH / 8; c++)
                a += gp[(size_t)(g * (ZCH / 8) + c) * (NB * ND)];
#pragma unroll
            for (int p = 0; p < NP / 8; p++)
                a += pm[(g * (NP / 8) + p) * ND + k];
            spart[g][kl] = a;
        }
        __syncthreads();
        if (t < KS) {
            float a = 0.f;
#pragma unroll
            for (int g = 0; g < 8; g++) a += spart[g][t];
            sk[t] = a / (float)NT;
        }
        __syncthreads();
        {   // GEMV1 partial: quad outputs, 4-way k-split
            const int q = t & 127, s = t >> 7;
            const int k0 = z * KS + s * 16;
            float4 acc = make_float4(0.f, 0.f, 0.f, 0.f);
#pragma unroll
            for (int j = 0; j < 16; j++) {
                float4 w = Wv4[(size_t)(k0 + j) * NQ + q];
                float  c = sk[s * 16 + j];
                acc.x += c * w.x; acc.y += c * w.y; acc.z += c * w.z; acc.w += c * w.w;
            }
            sacc[s][q] = acc;
        }
        __syncthreads();
        if (t < NQ) {
            float4 r = f4add(f4add(sacc[0][t], sacc[1][t]),
                             f4add(sacc[2][t], sacc[3][t]));
            g_vp4[z][b * NQ + t] = r;
        }
    }
    grid.sync();

    // ---------------- S3: GB — vbar combine + LN + GEMV2 partial -----------
    if (bid < NB * KZ) {
        const int b = bid & 3, z = bid >> 2, t = tid;
        float vb = bv[t];
#pragma unroll
        for (int c = 0; c < KZ; c++)
            vb += ((const float*)g_vp4[c])[b * ND + t];

        const float mu   = bsum512(vb, wred, &sbc[0]) / (float)ND;
        const float diff = vb - mu;
        const float var  = bsum512(diff * diff, wred, &sbc[1]) / (float)ND;
        const float inv  = rsqrtf(var + LN_EPS);
        const float nrm  = diff * inv * gamma[t] + beta[t];
        __syncthreads();
        if ((t >> 6) == z) ssn[t & 63] = nrm;
        __syncthreads();
        {
            const int q = t & 127, s = t >> 7;
            const int k0 = z * KS + s * 16;
            float4 acc = make_float4(0.f, 0.f, 0.f, 0.f);
#pragma unroll
            for (int j = 0; j < 16; j++) {
                float4 w = Wout4[(size_t)(k0 + j) * NQ + q];
                float  c = ssn[s * 16 + j];
                acc.x += c * w.x; acc.y += c * w.y; acc.z += c * w.z; acc.w += c * w.w;
            }
            sacc[s][q] = acc;
        }
        __syncthreads();
        if (t < NQ) {
            float4 r = f4add(f4add(sacc[0][t], sacc[1][t]),
                             f4add(sacc[2][t], sacc[3][t]));
            g_yp4[z][b * NQ + t] = r;
        }
    }
    grid.sync();

    // ---------------- S4: W — combine y + broadcast (all blocks) -----------
    {
        const int q = tid & 127;
#pragma unroll
        for (int b = 0; b < NB; b++) {
            float4 val = bout4[q];
#pragma unroll
            for (int z = 0; z < KZ; z++)
                val = f4add(val, g_yp4[z][b * NQ + q]);

            // each chunk = 32 rows = 4096 float4; 8 iterations x 512 threads
            for (int c = bid; c < WCH; c += NGRID) {
                float4* o = out4 + (size_t)b * NT * NQ +
                            (size_t)c * (32 * NQ) + tid;
#pragma unroll
                for (int it = 0; it < 8; it++) {
                    asm volatile("st.global.cs.v4.f32 [%0], {%1, %2, %3, %4};"
                                 :: "l"(o + (size_t)it * 512),
                                    "f"(val.x), "f"(val.y), "f"(val.z), "f"(val.w)
                                 : "memory");
                }
            }
        }
    }
}

// ---------------------------------------------------------------------------
extern "C" void kernel_launch(void* const* d_in, const int* in_sizes, int n_in,
                              void* d_out, int out_size) {
    const float4* x4    = (const float4*)d_in[0];
    const float*  pm    = (const float*)d_in[1];
    // d_in[2]=Wk, [3]=bk, [6]=Wq, [7]=bq unused: softmax over zero-state and
    // constant-in-m logits collapse to uniform attention weights.
    const float4* Wv4   = (const float4*)d_in[4];
    const float*  bv    = (const float*)d_in[5];
    const float*  gamma = (const float*)d_in[8];
    const float*  beta  = (const float*)d_in[9];
    const float4* Wout4 = (const float4*)d_in[10];
    const float4* bout4 = (const float4*)d_in[11];
    float4*       out4  = (float4*)d_out;

    void* args[] = { (void*)&x4, (void*)&pm, (void*)&Wv4, (void*)&bv,
                     (void*)&gamma, (void*)&beta, (void*)&Wout4,
                     (void*)&bout4, (void*)&out4 };
    cudaLaunchCooperativeKernel((const void*)titan_fused_kernel,
                                dim3(NGRID), dim3(512), args, 0, 0);
}